// round 2
// baseline (speedup 1.0000x reference)
#include <cuda_runtime.h>

#define BATCH 1024
#define RC 64
#define NL 24
#define QL 128
#define TB 4                    // batch rows per compute block
#define NCOMP (BATCH / TB)      // 256 compute blocks
#define NCOPY 928
#define NBLOCKS (NCOMP + NCOPY)
#define NTHREADS 256
#define NQ ((size_t)NL * BATCH * RC * QL)   // 201326592 queue elements

__device__ __forceinline__ float sigf(float x) { return 1.0f / (1.0f + __expf(-x)); }

__device__ __forceinline__ void qstore(float* __restrict__ dstq, size_t i4, float4 v)
{
    size_t e   = i4 * 4;
    size_t row = e >> 7;              // (layer*B + b)*RC + r
    unsigned t = (unsigned)(e & 127);
    float* p = dstq + row * 129 + t;
    __stcs(p + 0, v.x);
    __stcs(p + 1, v.y);
    __stcs(p + 2, v.z);
    __stcs(p + 3, v.w);
}

__global__ void __launch_bounds__(NTHREADS, 4)
wave_decoder_kernel(const float* __restrict__ x,
                    const float* __restrict__ features,
                    const float* __restrict__ queues,
                    const float* __restrict__ fc_h_w,
                    const float* __restrict__ fc_h_b,
                    const float* __restrict__ fc_c_w,
                    const float* __restrict__ fc_c_b,
                    const float* __restrict__ conv_w,
                    const float* __restrict__ conv_b,
                    const float* __restrict__ fc1_w,
                    const float* __restrict__ fc1_b,
                    const float* __restrict__ fc2_w,
                    const float* __restrict__ fc2_b,
                    float* __restrict__ out)
{
    if (blockIdx.x >= NCOMP) {
        // ------------------------------------------------------------------
        // COPY BLOCKS: queues (.., 128) -> out queue region (.., 129), t<128
        // 4 independent loads in flight per thread; streaming cache hints.
        // ------------------------------------------------------------------
        const float4* __restrict__ src = (const float4*)queues;
        float* __restrict__ dstq = out + BATCH;
        const size_t stride = (size_t)NCOPY * NTHREADS;
        const size_t n4 = NQ / 4;
        size_t i = (size_t)(blockIdx.x - NCOMP) * NTHREADS + threadIdx.x;

        for (; i + 3 * stride < n4; i += 4 * stride) {
            float4 v0 = __ldcs(&src[i]);
            float4 v1 = __ldcs(&src[i + stride]);
            float4 v2 = __ldcs(&src[i + 2 * stride]);
            float4 v3 = __ldcs(&src[i + 3 * stride]);
            qstore(dstq, i,              v0);
            qstore(dstq, i + stride,     v1);
            qstore(dstq, i + 2 * stride, v2);
            qstore(dstq, i + 3 * stride, v3);
        }
        for (; i < n4; i += stride) {
            float4 v = __ldcs(&src[i]);
            qstore(dstq, i, v);
        }
        return;
    }

    // ----------------------------------------------------------------------
    // COMPUTE BLOCKS: recurrent WaveNet cell for TB batch rows
    // thread j = threadIdx.x owns output channel j (0..255) of conv / fc1
    // ----------------------------------------------------------------------
    __shared__ __align__(16) float s_h[TB][RC];
    __shared__ __align__(16) float s_c[TB][RC];
    __shared__ __align__(16) float s_prev[TB][RC];
    __shared__ float s_co[TB][4 * RC];

    const int tid = threadIdx.x;
    const int b0  = blockIdx.x * TB;
    const int j   = tid;

    // ---- initial h, c = tanh(inp @ W^T + b), inp = [x, features] (33) ----
    {
        int t = tid >> 6, r = tid & 63;      // 256 threads == TB*RC elements
        int b = b0 + t;
        const float* wh = fc_h_w + r * 33;
        const float* wc = fc_c_w + r * 33;
        float ah = fc_h_b[r], ac = fc_c_b[r];
        float xv = x[b];
        ah += xv * wh[0];
        ac += xv * wc[0];
        const float* fb = features + b * 32;
        #pragma unroll
        for (int k = 0; k < 32; k++) {
            float f = fb[k];
            ah += f * wh[1 + k];
            ac += f * wc[1 + k];
        }
        s_h[t][r] = tanhf(ah);
        s_c[t][r] = tanhf(ac);
    }

    float yacc[TB];
    #pragma unroll
    for (int t = 0; t < TB; t++) yacc[t] = fc1_b[j];
    __syncthreads();

    float* __restrict__ outq = out + BATCH;

    for (int i = 0; i < NL; i++) {
        const int d = 1 << (i & 7);

        // ---- load dilated queue slice; write entry_h at t = 128 ----
        {
            int t = tid >> 6, r = tid & 63;
            int b = b0 + t;
            size_t rowi = (size_t)(i * BATCH + b) * RC + r;
            s_prev[t][r] = queues[rowi * QL + (QL - d)];
            outq[rowi * 129 + QL] = s_h[t][r];
        }
        __syncthreads();

        // ---- co[t][j] = prev @ W0^T + h @ W1^T + b  (weights in regs) ----
        float acc[TB];
        {
            float bias = conv_b[i * 256 + j];
            #pragma unroll
            for (int t = 0; t < TB; t++) acc[t] = bias;
        }
        const float4* __restrict__ wrow =
            (const float4*)(conv_w + (size_t)(i * 256 + j) * 128); // [r][2] interleaved
        #pragma unroll 4
        for (int rc = 0; rc < RC; rc += 4) {
            float4 wa = wrow[rc >> 1];       // w0[rc], w1[rc], w0[rc+1], w1[rc+1]
            float4 wb = wrow[(rc >> 1) + 1];
            #pragma unroll
            for (int t = 0; t < TB; t++) {
                float4 p  = *(const float4*)&s_prev[t][rc];
                float4 hh = *(const float4*)&s_h[t][rc];
                float a = acc[t];
                a += p.x * wa.x + hh.x * wa.y;
                a += p.y * wa.z + hh.y * wa.w;
                a += p.z * wb.x + hh.z * wb.y;
                a += p.w * wb.z + hh.w * wb.w;
                acc[t] = a;
            }
        }
        #pragma unroll
        for (int t = 0; t < TB; t++) s_co[t][j] = acc[t];
        __syncthreads();

        // ---- gate update ----
        {
            int t = tid >> 6, r = tid & 63;
            float ig = s_co[t][r];
            float cf = s_co[t][RC + r];
            float cg = s_co[t][2 * RC + r];
            float eg = s_co[t][3 * RC + r];
            float c = sigf(ig) * s_c[t][r] + tanhf(cf) * sigf(cg);
            s_c[t][r] = c;
            s_h[t][r] = sigf(eg) * tanhf(c);
        }
        __syncthreads();

        // ---- incremental fc1: yacc[t] += h[t] @ fc1_w[j, i*64 : i*64+64] ----
        const float4* __restrict__ f1 =
            (const float4*)(fc1_w + (size_t)j * (NL * RC) + i * RC);
        #pragma unroll 4
        for (int rc = 0; rc < RC; rc += 4) {
            float4 w = f1[rc >> 2];
            #pragma unroll
            for (int t = 0; t < TB; t++) {
                float4 hh = *(const float4*)&s_h[t][rc];
                yacc[t] += hh.x * w.x + hh.y * w.y + hh.z * w.z + hh.w * w.w;
            }
        }
        // no barrier needed: next iteration's slice-load only reads s_h and
        // writes s_prev, both safe until after the next two barriers
    }

    // ---- fc2: h_hat[b] = relu(y) @ fc2_w^T + fc2_b ----
    #pragma unroll
    for (int t = 0; t < TB; t++)
        s_co[t][j] = fmaxf(yacc[t], 0.0f) * fc2_w[j];
    __syncthreads();

    int w = tid >> 5, lane = tid & 31;
    if (w < TB) {
        float s = 0.0f;
        #pragma unroll
        for (int k = 0; k < 8; k++) s += s_co[w][lane + k * 32];
        #pragma unroll
        for (int o = 16; o > 0; o >>= 1) s += __shfl_xor_sync(0xffffffffu, s, o);
        if (lane == 0) out[b0 + w] = s + fc2_b[0];
    }
}

extern "C" void kernel_launch(void* const* d_in, const int* in_sizes, int n_in,
                              void* d_out, int out_size)
{
    const float* x        = (const float*)d_in[0];
    const float* features = (const float*)d_in[1];
    const float* queues   = (const float*)d_in[2];
    const float* fc_h_w   = (const float*)d_in[3];
    const float* fc_h_b   = (const float*)d_in[4];
    const float* fc_c_w   = (const float*)d_in[5];
    const float* fc_c_b   = (const float*)d_in[6];
    const float* conv_w   = (const float*)d_in[7];
    const float* conv_b   = (const float*)d_in[8];
    const float* fc1_w    = (const float*)d_in[9];
    const float* fc1_b    = (const float*)d_in[10];
    const float* fc2_w    = (const float*)d_in[11];
    const float* fc2_b    = (const float*)d_in[12];
    float* out = (float*)d_out;

    wave_decoder_kernel<<<NBLOCKS, NTHREADS>>>(
        x, features, queues, fc_h_w, fc_h_b, fc_c_w, fc_c_b,
        conv_w, conv_b, fc1_w, fc1_b, fc2_w, fc2_b, out);
}

// round 3
// speedup vs baseline: 1.1998x; 1.1998x over previous
#include <cuda_runtime.h>

#define BATCH 1024
#define RC 64
#define NL 24
#define QL 128
#define TB 8                    // batch rows per compute block
#define NCOMP (BATCH / TB)      // 128 compute blocks
#define NCOPY 896
#define NBLOCKS (NCOMP + NCOPY)
#define NTHREADS 256
#define NQ ((size_t)NL * BATCH * RC * QL)   // 201326592 queue elements
#define NROWS (NQ / 128)                    // 1572864 rows of 128 floats

__device__ __forceinline__ float sigf(float x) { return 1.0f / (1.0f + __expf(-x)); }

// Store one 128-float row (held as float4 v per lane) to dstq + R*129,
// realigned so the bulk goes out as one aligned STG.128 per lane.
__device__ __forceinline__ void store_row(float* __restrict__ dstq, size_t R,
                                          int lane, float4 v)
{
    float* base = dstq + R * 129;
    unsigned m = (unsigned)(R & 3);          // base misalignment in floats
    if (m == 0) {
        *(float4*)(base + 4 * lane) = v;
        return;
    }
    unsigned s = 4 - m;                      // shift: first aligned float index
    float nx = __shfl_down_sync(0xffffffffu, v.x, 1);
    float ny = __shfl_down_sync(0xffffffffu, v.y, 1);
    float nz = __shfl_down_sync(0xffffffffu, v.z, 1);
    float4 w;
    if (s == 1)      w = make_float4(v.y, v.z, v.w, nx);
    else if (s == 2) w = make_float4(v.z, v.w, nx, ny);
    else             w = make_float4(v.w, nx, ny, nz);
    if (lane < 31)
        *(float4*)(base + s + 4 * lane) = w; // j in [s, s+124), 16B aligned
    if (lane == 0) {                         // head floats j = 0..s-1
        base[0] = v.x;
        if (s >= 2) base[1] = v.y;
        if (s >= 3) base[2] = v.z;
    }
    if (lane == 31) {                        // tail floats j = s+124..127
        base[127] = v.w;
        if (s <= 2) base[126] = v.z;
        if (s <= 1) base[125] = v.y;
    }
}

__global__ void __launch_bounds__(NTHREADS)
wave_decoder_kernel(const float* __restrict__ x,
                    const float* __restrict__ features,
                    const float* __restrict__ queues,
                    const float* __restrict__ fc_h_w,
                    const float* __restrict__ fc_h_b,
                    const float* __restrict__ fc_c_w,
                    const float* __restrict__ fc_c_b,
                    const float* __restrict__ conv_w,
                    const float* __restrict__ conv_b,
                    const float* __restrict__ fc1_w,
                    const float* __restrict__ fc1_b,
                    const float* __restrict__ fc2_w,
                    const float* __restrict__ fc2_b,
                    float* __restrict__ out)
{
    if (blockIdx.x >= NCOMP) {
        // ------------------------------------------------------------------
        // COPY BLOCKS: queues (.., 128) -> out queue region (.., 129), t<128
        // One row (128 floats) per warp-step; STG.128 via shuffle realign.
        // ------------------------------------------------------------------
        const float4* __restrict__ src = (const float4*)queues;
        float* __restrict__ dstq = out + BATCH;
        const int lane = threadIdx.x & 31;
        const size_t nw = (size_t)NCOPY * (NTHREADS / 32);     // total copy warps
        size_t R = (size_t)(blockIdx.x - NCOMP) * (NTHREADS / 32)
                 + (threadIdx.x >> 5);

        for (; R + 3 * nw < NROWS; R += 4 * nw) {
            float4 v0 = __ldcs(&src[(R)          * 32 + lane]);
            float4 v1 = __ldcs(&src[(R + nw)     * 32 + lane]);
            float4 v2 = __ldcs(&src[(R + 2 * nw) * 32 + lane]);
            float4 v3 = __ldcs(&src[(R + 3 * nw) * 32 + lane]);
            store_row(dstq, R,          lane, v0);
            store_row(dstq, R + nw,     lane, v1);
            store_row(dstq, R + 2 * nw, lane, v2);
            store_row(dstq, R + 3 * nw, lane, v3);
        }
        for (; R < NROWS; R += nw) {
            float4 v = __ldcs(&src[R * 32 + lane]);
            store_row(dstq, R, lane, v);
        }
        return;
    }

    // ----------------------------------------------------------------------
    // COMPUTE BLOCKS: recurrent WaveNet cell for TB batch rows
    // thread j = threadIdx.x owns output channel j (0..255) of conv / fc1
    // ----------------------------------------------------------------------
    __shared__ __align__(16) float s_h[TB][RC];
    __shared__ __align__(16) float s_c[TB][RC];
    __shared__ __align__(16) float s_prev[TB][RC];
    __shared__ float s_co[TB][4 * RC];

    const int tid = threadIdx.x;
    const int b0  = blockIdx.x * TB;
    const int j   = tid;

    // ---- initial h, c = tanh(inp @ W^T + b), inp = [x, features] (33) ----
    for (int idx = tid; idx < TB * RC; idx += NTHREADS) {
        int t = idx >> 6, r = idx & 63;
        int b = b0 + t;
        const float* wh = fc_h_w + r * 33;
        const float* wc = fc_c_w + r * 33;
        float ah = fc_h_b[r], ac = fc_c_b[r];
        float xv = x[b];
        ah += xv * wh[0];
        ac += xv * wc[0];
        const float* fb = features + b * 32;
        #pragma unroll
        for (int k = 0; k < 32; k++) {
            float f = fb[k];
            ah += f * wh[1 + k];
            ac += f * wc[1 + k];
        }
        s_h[t][r] = tanhf(ah);
        s_c[t][r] = tanhf(ac);
    }

    float yacc[TB];
    #pragma unroll
    for (int t = 0; t < TB; t++) yacc[t] = fc1_b[j];
    __syncthreads();

    float* __restrict__ outq = out + BATCH;

    for (int i = 0; i < NL; i++) {
        const int d = 1 << (i & 7);

        // ---- load dilated queue slice; write entry_h at t = 128 ----
        for (int idx = tid; idx < TB * RC; idx += NTHREADS) {
            int t = idx >> 6, r = idx & 63;
            int b = b0 + t;
            size_t rowi = (size_t)(i * BATCH + b) * RC + r;
            s_prev[t][r] = queues[rowi * QL + (QL - d)];
            outq[rowi * 129 + QL] = s_h[t][r];
        }
        __syncthreads();

        // ---- co[t][j] = prev @ W0^T + h @ W1^T + b  (weights in regs) ----
        float acc[TB];
        {
            float bias = conv_b[i * 256 + j];
            #pragma unroll
            for (int t = 0; t < TB; t++) acc[t] = bias;
        }
        const float4* __restrict__ wrow =
            (const float4*)(conv_w + (size_t)(i * 256 + j) * 128); // [r][2] interleaved
        #pragma unroll 4
        for (int rc = 0; rc < RC; rc += 4) {
            float4 wa = wrow[rc >> 1];       // w0[rc], w1[rc], w0[rc+1], w1[rc+1]
            float4 wb = wrow[(rc >> 1) + 1];
            #pragma unroll
            for (int t = 0; t < TB; t++) {
                float4 p  = *(const float4*)&s_prev[t][rc];
                float4 hh = *(const float4*)&s_h[t][rc];
                float a = acc[t];
                a += p.x * wa.x + hh.x * wa.y;
                a += p.y * wa.z + hh.y * wa.w;
                a += p.z * wb.x + hh.z * wb.y;
                a += p.w * wb.z + hh.w * wb.w;
                acc[t] = a;
            }
        }
        #pragma unroll
        for (int t = 0; t < TB; t++) s_co[t][j] = acc[t];
        __syncthreads();

        // ---- gate update ----
        for (int idx = tid; idx < TB * RC; idx += NTHREADS) {
            int t = idx >> 6, r = idx & 63;
            float ig = s_co[t][r];
            float cf = s_co[t][RC + r];
            float cg = s_co[t][2 * RC + r];
            float eg = s_co[t][3 * RC + r];
            float c = sigf(ig) * s_c[t][r] + tanhf(cf) * sigf(cg);
            s_c[t][r] = c;
            s_h[t][r] = sigf(eg) * tanhf(c);
        }
        __syncthreads();

        // ---- incremental fc1: yacc[t] += h[t] @ fc1_w[j, i*64 : i*64+64] ----
        const float4* __restrict__ f1 =
            (const float4*)(fc1_w + (size_t)j * (NL * RC) + i * RC);
        #pragma unroll 4
        for (int rc = 0; rc < RC; rc += 4) {
            float4 w = f1[rc >> 2];
            #pragma unroll
            for (int t = 0; t < TB; t++) {
                float4 hh = *(const float4*)&s_h[t][rc];
                yacc[t] += hh.x * w.x + hh.y * w.y + hh.z * w.z + hh.w * w.w;
            }
        }
        // no barrier needed: next iteration's slice-load only reads s_h and
        // writes s_prev, both safe until after the next two barriers
    }

    // ---- fc2: h_hat[b] = relu(y) @ fc2_w^T + fc2_b ----
    #pragma unroll
    for (int t = 0; t < TB; t++)
        s_co[t][j] = fmaxf(yacc[t], 0.0f) * fc2_w[j];
    __syncthreads();

    int w = tid >> 5, lane = tid & 31;   // 8 warps == TB rows
    float s = 0.0f;
    #pragma unroll
    for (int k = 0; k < 8; k++) s += s_co[w][lane + k * 32];
    #pragma unroll
    for (int o = 16; o > 0; o >>= 1) s += __shfl_xor_sync(0xffffffffu, s, o);
    if (lane == 0) out[b0 + w] = s + fc2_b[0];
}

extern "C" void kernel_launch(void* const* d_in, const int* in_sizes, int n_in,
                              void* d_out, int out_size)
{
    const float* x        = (const float*)d_in[0];
    const float* features = (const float*)d_in[1];
    const float* queues   = (const float*)d_in[2];
    const float* fc_h_w   = (const float*)d_in[3];
    const float* fc_h_b   = (const float*)d_in[4];
    const float* fc_c_w   = (const float*)d_in[5];
    const float* fc_c_b   = (const float*)d_in[6];
    const float* conv_w   = (const float*)d_in[7];
    const float* conv_b   = (const float*)d_in[8];
    const float* fc1_w    = (const float*)d_in[9];
    const float* fc1_b    = (const float*)d_in[10];
    const float* fc2_w    = (const float*)d_in[11];
    const float* fc2_b    = (const float*)d_in[12];
    float* out = (float*)d_out;

    wave_decoder_kernel<<<NBLOCKS, NTHREADS>>>(
        x, features, queues, fc_h_w, fc_h_b, fc_c_w, fc_c_b,
        conv_w, conv_b, fc1_w, fc1_b, fc2_w, fc2_b, out);
}

// round 4
// speedup vs baseline: 1.2383x; 1.0321x over previous
#include <cuda_runtime.h>

#define BATCH 1024
#define RC 64
#define NL 24
#define QL 128
#define TB 8                     // batch rows per compute block
#define NCOMP (BATCH / TB)       // 128 compute blocks
#define NTHREADS 256
#define NQ ((size_t)NL * BATCH * RC * QL)   // 201326592 queue elements
#define NROWS (NQ / 128)                    // 1572864 rows of 128 floats
#define RPW 64                              // rows per copy warp
#define WARPS_PER_BLK 8
#define NCOPY ((int)(NROWS / (RPW * WARPS_PER_BLK)))   // 3072 copy blocks

__device__ __forceinline__ float sigf(float x) { return 1.0f / (1.0f + __expf(-x)); }

// Store one 128-float row (held as float4 v per lane) to dstq + R*129,
// realigned so the bulk goes out as one aligned STG.128 per lane.
__device__ __forceinline__ void store_row(float* __restrict__ dstq, size_t R,
                                          int lane, float4 v)
{
    float* base = dstq + R * 129;
    unsigned m = (unsigned)(R & 3);          // base misalignment in floats
    if (m == 0) {
        *(float4*)(base + 4 * lane) = v;
        return;
    }
    unsigned s = 4 - m;                      // shift: first aligned float index
    float nx = __shfl_down_sync(0xffffffffu, v.x, 1);
    float ny = __shfl_down_sync(0xffffffffu, v.y, 1);
    float nz = __shfl_down_sync(0xffffffffu, v.z, 1);
    float4 w;
    if (s == 1)      w = make_float4(v.y, v.z, v.w, nx);
    else if (s == 2) w = make_float4(v.z, v.w, nx, ny);
    else             w = make_float4(v.w, nx, ny, nz);
    if (lane < 31)
        *(float4*)(base + s + 4 * lane) = w; // 16B-aligned bulk
    if (lane == 0) {                         // head floats j = 0..s-1
        base[0] = v.x;
        if (s >= 2) base[1] = v.y;
        if (s >= 3) base[2] = v.z;
    }
    if (lane == 31) {                        // tail floats j = s+124..127
        base[127] = v.w;
        if (s <= 2) base[126] = v.z;
        if (s <= 1) base[125] = v.y;
    }
}

// ---------------------------------------------------------------------------
// COPY KERNEL: queues (.., 128) -> out queue region (.., 129), t < 128.
// Each warp owns RPW contiguous rows; 4-row unroll -> 2KB contiguous reads.
// ---------------------------------------------------------------------------
__global__ void __launch_bounds__(NTHREADS)
queue_copy_kernel(const float* __restrict__ queues, float* __restrict__ out)
{
    const float4* __restrict__ src = (const float4*)queues;
    float* __restrict__ dstq = out + BATCH;
    const int lane = threadIdx.x & 31;
    size_t R = ((size_t)blockIdx.x * WARPS_PER_BLK + (threadIdx.x >> 5)) * RPW;

    #pragma unroll 1
    for (int it = 0; it < RPW / 4; it++, R += 4) {
        float4 v0 = __ldcs(&src[(R)     * 32 + lane]);
        float4 v1 = __ldcs(&src[(R + 1) * 32 + lane]);
        float4 v2 = __ldcs(&src[(R + 2) * 32 + lane]);
        float4 v3 = __ldcs(&src[(R + 3) * 32 + lane]);
        store_row(dstq, R,     lane, v0);
        store_row(dstq, R + 1, lane, v1);
        store_row(dstq, R + 2, lane, v2);
        store_row(dstq, R + 3, lane, v3);
    }
}

// ---------------------------------------------------------------------------
// COMPUTE KERNEL: recurrent WaveNet cell for TB batch rows per block.
// thread j owns output channel j (0..255) of conv / fc1.
// ---------------------------------------------------------------------------
__global__ void __launch_bounds__(NTHREADS)
wave_compute_kernel(const float* __restrict__ x,
                    const float* __restrict__ features,
                    const float* __restrict__ queues,
                    const float* __restrict__ fc_h_w,
                    const float* __restrict__ fc_h_b,
                    const float* __restrict__ fc_c_w,
                    const float* __restrict__ fc_c_b,
                    const float* __restrict__ conv_w,
                    const float* __restrict__ conv_b,
                    const float* __restrict__ fc1_w,
                    const float* __restrict__ fc1_b,
                    const float* __restrict__ fc2_w,
                    const float* __restrict__ fc2_b,
                    float* __restrict__ out)
{
    __shared__ __align__(16) float s_h[TB][RC];
    __shared__ __align__(16) float s_c[TB][RC];
    __shared__ __align__(16) float s_prev[TB][RC];
    __shared__ float s_co[TB][4 * RC];

    const int tid = threadIdx.x;
    const int b0  = blockIdx.x * TB;
    const int j   = tid;

    // ---- initial h, c = tanh(inp @ W^T + b), inp = [x, features] (33) ----
    for (int idx = tid; idx < TB * RC; idx += NTHREADS) {
        int t = idx >> 6, r = idx & 63;
        int b = b0 + t;
        const float* wh = fc_h_w + r * 33;
        const float* wc = fc_c_w + r * 33;
        float ah = fc_h_b[r], ac = fc_c_b[r];
        float xv = x[b];
        ah += xv * wh[0];
        ac += xv * wc[0];
        const float* fb = features + b * 32;
        #pragma unroll
        for (int k = 0; k < 32; k++) {
            float f = fb[k];
            ah += f * wh[1 + k];
            ac += f * wc[1 + k];
        }
        s_h[t][r] = tanhf(ah);
        s_c[t][r] = tanhf(ac);
    }

    float yacc[TB];
    #pragma unroll
    for (int t = 0; t < TB; t++) yacc[t] = fc1_b[j];
    __syncthreads();

    float* __restrict__ outq = out + BATCH;

    for (int i = 0; i < NL; i++) {
        const int d = 1 << (i & 7);

        // ---- load dilated queue slice; write entry_h at t = 128 ----
        for (int idx = tid; idx < TB * RC; idx += NTHREADS) {
            int t = idx >> 6, r = idx & 63;
            int b = b0 + t;
            size_t rowi = (size_t)(i * BATCH + b) * RC + r;
            s_prev[t][r] = queues[rowi * QL + (QL - d)];
            outq[rowi * 129 + QL] = s_h[t][r];
        }
        __syncthreads();

        // ---- co[t][j] = prev @ W0^T + h @ W1^T + b  (weights in regs) ----
        float acc[TB];
        {
            float bias = conv_b[i * 256 + j];
            #pragma unroll
            for (int t = 0; t < TB; t++) acc[t] = bias;
        }
        const float4* __restrict__ wrow =
            (const float4*)(conv_w + (size_t)(i * 256 + j) * 128); // [r][2] interleaved
        #pragma unroll 4
        for (int rc = 0; rc < RC; rc += 4) {
            float4 wa = wrow[rc >> 1];       // w0[rc], w1[rc], w0[rc+1], w1[rc+1]
            float4 wb = wrow[(rc >> 1) + 1];
            #pragma unroll
            for (int t = 0; t < TB; t++) {
                float4 p  = *(const float4*)&s_prev[t][rc];
                float4 hh = *(const float4*)&s_h[t][rc];
                float a = acc[t];
                a += p.x * wa.x + hh.x * wa.y;
                a += p.y * wa.z + hh.y * wa.w;
                a += p.z * wb.x + hh.z * wb.y;
                a += p.w * wb.z + hh.w * wb.w;
                acc[t] = a;
            }
        }
        #pragma unroll
        for (int t = 0; t < TB; t++) s_co[t][j] = acc[t];
        __syncthreads();

        // ---- gate update ----
        for (int idx = tid; idx < TB * RC; idx += NTHREADS) {
            int t = idx >> 6, r = idx & 63;
            float ig = s_co[t][r];
            float cf = s_co[t][RC + r];
            float cg = s_co[t][2 * RC + r];
            float eg = s_co[t][3 * RC + r];
            float c = sigf(ig) * s_c[t][r] + tanhf(cf) * sigf(cg);
            s_c[t][r] = c;
            s_h[t][r] = sigf(eg) * tanhf(c);
        }
        __syncthreads();

        // ---- incremental fc1: yacc[t] += h[t] @ fc1_w[j, i*64 : i*64+64] ----
        const float4* __restrict__ f1 =
            (const float4*)(fc1_w + (size_t)j * (NL * RC) + i * RC);
        #pragma unroll 4
        for (int rc = 0; rc < RC; rc += 4) {
            float4 w = f1[rc >> 2];
            #pragma unroll
            for (int t = 0; t < TB; t++) {
                float4 hh = *(const float4*)&s_h[t][rc];
                yacc[t] += hh.x * w.x + hh.y * w.y + hh.z * w.z + hh.w * w.w;
            }
        }
        // no barrier needed: next iteration's slice-load only reads s_h and
        // writes s_prev, both safe until after the next two barriers
    }

    // ---- fc2: h_hat[b] = relu(y) @ fc2_w^T + fc2_b ----
    #pragma unroll
    for (int t = 0; t < TB; t++)
        s_co[t][j] = fmaxf(yacc[t], 0.0f) * fc2_w[j];
    __syncthreads();

    int w = tid >> 5, lane = tid & 31;   // 8 warps == TB rows
    float s = 0.0f;
    #pragma unroll
    for (int k = 0; k < 8; k++) s += s_co[w][lane + k * 32];
    #pragma unroll
    for (int o = 16; o > 0; o >>= 1) s += __shfl_xor_sync(0xffffffffu, s, o);
    if (lane == 0) out[b0 + w] = s + fc2_b[0];
}

extern "C" void kernel_launch(void* const* d_in, const int* in_sizes, int n_in,
                              void* d_out, int out_size)
{
    const float* x        = (const float*)d_in[0];
    const float* features = (const float*)d_in[1];
    const float* queues   = (const float*)d_in[2];
    const float* fc_h_w   = (const float*)d_in[3];
    const float* fc_h_b   = (const float*)d_in[4];
    const float* fc_c_w   = (const float*)d_in[5];
    const float* fc_c_b   = (const float*)d_in[6];
    const float* conv_w   = (const float*)d_in[7];
    const float* conv_b   = (const float*)d_in[8];
    const float* fc1_w    = (const float*)d_in[9];
    const float* fc1_b    = (const float*)d_in[10];
    const float* fc2_w    = (const float*)d_in[11];
    const float* fc2_b    = (const float*)d_in[12];
    float* out = (float*)d_out;

    // Fork a second (low-priority) stream off the capturing stream so the
    // compute and copy kernels run CONCURRENTLY inside the captured graph.
    int prLo = 0, prHi = 0;
    cudaDeviceGetStreamPriorityRange(&prLo, &prHi);
    cudaStream_t s1;
    cudaStreamCreateWithPriority(&s1, cudaStreamNonBlocking, prLo);
    cudaEvent_t evFork, evJoin;
    cudaEventCreateWithFlags(&evFork, cudaEventDisableTiming);
    cudaEventCreateWithFlags(&evJoin, cudaEventDisableTiming);

    cudaEventRecord(evFork, 0);          // fork point (before any kernel)
    cudaStreamWaitEvent(s1, evFork, 0);

    wave_compute_kernel<<<NCOMP, NTHREADS>>>(
        x, features, queues, fc_h_w, fc_h_b, fc_c_w, fc_c_b,
        conv_w, conv_b, fc1_w, fc1_b, fc2_w, fc2_b, out);

    queue_copy_kernel<<<NCOPY, NTHREADS, 0, s1>>>(queues, out);

    cudaEventRecord(evJoin, s1);         // join copy stream back
    cudaStreamWaitEvent(0, evJoin, 0);

    cudaStreamDestroy(s1);
    cudaEventDestroy(evFork);
    cudaEventDestroy(evJoin);
}